// round 5
// baseline (speedup 1.0000x reference)
#include <cuda_runtime.h>
#include <cstdint>

// Problem constants
#define R_TOTAL 24576   // B*T*N = 2*12*1024
#define DMODEL  128
#define NKEYS   1024
#define NHEADS  8
#define NITEMS  768     // 192 heads x 4 query-chunks of 256

typedef unsigned long long u64;

// ---------- packed f32x2 helpers ----------
__device__ __forceinline__ u64 pk2(float x, float y) {
    u64 r; asm("mov.b64 %0, {%1,%2};" : "=l"(r) : "f"(x), "f"(y)); return r;
}
__device__ __forceinline__ float2 upk2(u64 v) {
    float2 r; asm("mov.b64 {%0,%1}, %2;" : "=f"(r.x), "=f"(r.y) : "l"(v)); return r;
}
__device__ __forceinline__ u64 fma2(u64 a, u64 b, u64 c) {
    u64 d; asm("fma.rn.f32x2 %0, %1, %2, %3;" : "=l"(d) : "l"(a), "l"(b), "l"(c)); return d;
}
__device__ __forceinline__ u64 mul2(u64 a, u64 b) {
    u64 d; asm("mul.rn.f32x2 %0, %1, %2;" : "=l"(d) : "l"(a), "l"(b)); return d;
}
__device__ __forceinline__ u64 add2(u64 a, u64 b) {
    u64 d; asm("add.rn.f32x2 %0, %1, %2;" : "=l"(d) : "l"(a), "l"(b)); return d;
}
__device__ __forceinline__ float ex2(float x) {
    float y; asm("ex2.approx.f32 %0, %1;" : "=f"(y) : "f"(x)); return y;
}
__device__ __forceinline__ void cp16(void* dst, const void* src) {
    uint32_t d = (uint32_t)__cvta_generic_to_shared(dst);
    asm volatile("cp.async.cg.shared.global [%0], [%1], 16;" :: "r"(d), "l"(src));
}
__device__ __forceinline__ void cp_commit() {
    asm volatile("cp.async.commit_group;");
}
template<int N> __device__ __forceinline__ void cp_wait() {
    asm volatile("cp.async.wait_group %0;" :: "n"(N));
}

// ---------- scratch (no cudaMalloc allowed) ----------
__device__ float g_qh[R_TOTAL * DMODEL];   // head-major (bt,h,n,hd)
__device__ float g_kh[R_TOTAL * DMODEL];
__device__ float g_vh[R_TOTAL * DMODEL];
__device__ float g_ao[R_TOTAL * DMODEL];   // attention out, row-major (r, d)
__device__ unsigned int g_ctr;             // work-queue counter (memset per launch)

// ============================================================================
// GEMM core: out[r,j] = sum_c X[r,c]*W[j,c] + bias[j]; 128 rows/block, N=K=128
// Register-prefetch pipeline: chunk kk+1 LDG issued while chunk kk computes.
// ============================================================================
__device__ __forceinline__ void gemm_body(
    const float* __restrict__ X, const float* __restrict__ W,
    const float* __restrict__ bias, float* __restrict__ out,
    int row0, int headmajor)
{
    __shared__ float Xs[32][132];
    __shared__ float Ws[32][132];

    const int tid = threadIdx.x;
    const int ti  = tid >> 4;
    const int tj  = tid & 15;

    // per-thread gmem addresses for the 4 load slots
    int li[4], lc4[4];
    #pragma unroll
    for (int it = 0; it < 4; ++it) {
        int idx = it * 256 + tid;
        li[it]  = idx >> 3;          // row 0..127
        lc4[it] = idx & 7;           // float4 slot 0..7
    }

    float4 xr[4], wr[4];
    #pragma unroll
    for (int it = 0; it < 4; ++it) {
        xr[it] = *(const float4*)(X + (size_t)(row0 + li[it]) * 128 + lc4[it] * 4);
        wr[it] = *(const float4*)(W + (size_t)li[it] * 128 + lc4[it] * 4);
    }

    u64 acc[8][4];
    #pragma unroll
    for (int i = 0; i < 8; ++i)
        #pragma unroll
        for (int jp = 0; jp < 4; ++jp) acc[i][jp] = 0ull;

    for (int kk = 0; kk < 128; kk += 32) {
        // stage current chunk (transposed) into smem
        #pragma unroll
        for (int it = 0; it < 4; ++it) {
            int i = li[it], c0 = lc4[it] * 4;
            Xs[c0+0][i] = xr[it].x; Xs[c0+1][i] = xr[it].y;
            Xs[c0+2][i] = xr[it].z; Xs[c0+3][i] = xr[it].w;
            Ws[c0+0][i] = wr[it].x; Ws[c0+1][i] = wr[it].y;
            Ws[c0+2][i] = wr[it].z; Ws[c0+3][i] = wr[it].w;
        }
        __syncthreads();

        // prefetch next chunk while computing this one
        if (kk < 96) {
            #pragma unroll
            for (int it = 0; it < 4; ++it) {
                xr[it] = *(const float4*)(X + (size_t)(row0 + li[it]) * 128 + kk + 32 + lc4[it] * 4);
                wr[it] = *(const float4*)(W + (size_t)li[it] * 128 + kk + 32 + lc4[it] * 4);
            }
        }

        #pragma unroll
        for (int c = 0; c < 32; ++c) {
            float4 a0 = *(const float4*)(&Xs[c][ti * 8]);
            float4 a1 = *(const float4*)(&Xs[c][ti * 8 + 4]);
            const ulonglong2* bp = (const ulonglong2*)(&Ws[c][tj * 8]);
            ulonglong2 bA = bp[0], bB = bp[1];
            u64 b2[4] = { bA.x, bA.y, bB.x, bB.y };
            float a[8] = {a0.x, a0.y, a0.z, a0.w, a1.x, a1.y, a1.z, a1.w};
            #pragma unroll
            for (int i = 0; i < 8; ++i) {
                u64 ad = pk2(a[i], a[i]);
                #pragma unroll
                for (int jp = 0; jp < 4; ++jp)
                    acc[i][jp] = fma2(ad, b2[jp], acc[i][jp]);
            }
        }
        __syncthreads();
    }

    #pragma unroll
    for (int i = 0; i < 8; ++i) {
        int r = row0 + ti * 8 + i;
        #pragma unroll
        for (int jp = 0; jp < 4; ++jp) {
            float2 v = upk2(acc[i][jp]);
            int j0 = tj * 8 + jp * 2;
            float o0 = v.x + bias[j0];
            float o1 = v.y + bias[j0 + 1];
            if (headmajor) {
                int bt = r >> 10, n = r & 1023;
                int h  = j0 >> 4, hd = j0 & 15;
                float* dst = out + (((size_t)(bt * NHEADS + h)) << 14) + (n << 4) + hd;
                dst[0] = o0; dst[1] = o1;
            } else {
                out[(size_t)r * 128 + j0]     = o0;
                out[(size_t)r * 128 + j0 + 1] = o1;
            }
        }
    }
}

__global__ __launch_bounds__(256) void gemm_qkv(
    const float* __restrict__ Xq, const float* __restrict__ Xk,
    const float* __restrict__ Xv,
    const float* __restrict__ Wq, const float* __restrict__ Wk,
    const float* __restrict__ Wv,
    const float* __restrict__ bq, const float* __restrict__ bk,
    const float* __restrict__ bv,
    float* __restrict__ oq, float* __restrict__ ok, float* __restrict__ ov)
{
    const int which = blockIdx.y;
    const float* X = (which == 0) ? Xq : (which == 1) ? Xk : Xv;
    const float* W = (which == 0) ? Wq : (which == 1) ? Wk : Wv;
    const float* b = (which == 0) ? bq : (which == 1) ? bk : bv;
    float*       o = (which == 0) ? oq : (which == 1) ? ok : ov;
    gemm_body(X, W, b, o, blockIdx.x * 128, 1);
}

__global__ __launch_bounds__(256) void gemm_o(
    const float* __restrict__ X, const float* __restrict__ W,
    const float* __restrict__ bias, float* __restrict__ out)
{
    gemm_body(X, W, bias, out, blockIdx.x * 128, 0);
}

// ============================================================================
// Attention v5: persistent CTAs + atomic work queue (no wave quantization).
// Grid 592 = 148*4, block 128, QPT=2 per item (256 queries), 768 items.
// K/V streamed in 128-key tiles, double-buffered cp.async (32 KB smem).
// ============================================================================
#define QPT 2
#define KPT 2
#define TK  128
#define NTILES (NKEYS / TK)

__global__ __launch_bounds__(128, 4) void attn_kernel(
    const float* __restrict__ Qh, const float* __restrict__ Kh,
    const float* __restrict__ Vh, float* __restrict__ Oc)
{
    __shared__ float Ks[2][TK * 16];   // 2 x 8 KB
    __shared__ float Vs[2][TK * 16];   // 2 x 8 KB
    __shared__ unsigned int sh_item;

    const int tid = threadIdx.x;
    const float sc = 0.25f * 1.4426950408889634f;   // (1/sqrt16)*log2(e)
    const u64 scale2 = pk2(sc, sc);

    for (;;) {
        if (tid == 0) sh_item = atomicAdd(&g_ctr, 1u);
        __syncthreads();
        const unsigned int item = sh_item;
        __syncthreads();
        if (item >= NITEMS) break;

        const int bth = item >> 2;          // 0..191
        const int qc  = item & 3;           // 0..3

        const float* Kg = Kh + (size_t)bth * 16384;
        const float* Vg = Vh + (size_t)bth * 16384;

        // prefetch tile 0
        #pragma unroll
        for (int i = 0; i < 4; ++i) {
            int idx = tid + i * 128;
            cp16(&Ks[0][idx * 4], Kg + idx * 4);
            cp16(&Vs[0][idx * 4], Vg + idx * 4);
        }
        cp_commit();

        // load + prescale queries
        u64 q2[QPT][8];
        #pragma unroll
        for (int q = 0; q < QPT; ++q) {
            int n = qc * (128 * QPT) + q * 128 + tid;
            const float* qp = Qh + (size_t)bth * 16384 + n * 16;
            #pragma unroll
            for (int r = 0; r < 4; ++r) {
                ulonglong2 qv = *(const ulonglong2*)(qp + r * 4);
                q2[q][r * 2]     = mul2(qv.x, scale2);
                q2[q][r * 2 + 1] = mul2(qv.y, scale2);
            }
        }

        u64 acc[QPT][8];
        #pragma unroll
        for (int q = 0; q < QPT; ++q)
            #pragma unroll
            for (int r = 0; r < 8; ++r) acc[q][r] = 0ull;
        float l[QPT];
        #pragma unroll
        for (int q = 0; q < QPT; ++q) l[q] = 0.0f;

        #pragma unroll 1
        for (int t = 0; t < NTILES; ++t) {
            const int buf = t & 1;
            if (t < NTILES - 1) {
                const int nb = buf ^ 1;
                const float* kp = Kg + (t + 1) * TK * 16;
                const float* vp = Vg + (t + 1) * TK * 16;
                #pragma unroll
                for (int i = 0; i < 4; ++i) {
                    int idx = tid + i * 128;
                    cp16(&Ks[nb][idx * 4], kp + idx * 4);
                    cp16(&Vs[nb][idx * 4], vp + idx * 4);
                }
                cp_commit();
                cp_wait<1>();
            } else {
                cp_wait<0>();
            }
            __syncthreads();

            const float* Kt = Ks[buf];
            const float* Vt = Vs[buf];

            #pragma unroll 2
            for (int j = 0; j < TK; j += KPT) {
                u64 sa[KPT][QPT], sb[KPT][QPT];
                #pragma unroll
                for (int kk = 0; kk < KPT; ++kk) {
                    const ulonglong2* kj = (const ulonglong2*)(Kt + (j + kk) * 16);
                    ulonglong2 k0 = kj[0], k1 = kj[1], k2v = kj[2], k3 = kj[3];
                    #pragma unroll
                    for (int q = 0; q < QPT; ++q) {
                        u64 a = mul2(q2[q][0], k0.x);
                        u64 b = mul2(q2[q][1], k0.y);
                        a = fma2(q2[q][2], k1.x, a);
                        b = fma2(q2[q][3], k1.y, b);
                        a = fma2(q2[q][4], k2v.x, a);
                        b = fma2(q2[q][5], k2v.y, b);
                        a = fma2(q2[q][6], k3.x, a);
                        b = fma2(q2[q][7], k3.y, b);
                        sa[kk][q] = a; sb[kk][q] = b;
                    }
                }
                float p[KPT][QPT];
                #pragma unroll
                for (int kk = 0; kk < KPT; ++kk)
                    #pragma unroll
                    for (int q = 0; q < QPT; ++q) {
                        float2 f = upk2(add2(sa[kk][q], sb[kk][q]));
                        p[kk][q] = ex2(f.x + f.y);
                        l[q] += p[kk][q];
                    }
                #pragma unroll
                for (int kk = 0; kk < KPT; ++kk) {
                    const ulonglong2* vj = (const ulonglong2*)(Vt + (j + kk) * 16);
                    ulonglong2 v0 = vj[0], v1 = vj[1], v2v = vj[2], v3 = vj[3];
                    #pragma unroll
                    for (int q = 0; q < QPT; ++q) {
                        u64 p2 = pk2(p[kk][q], p[kk][q]);
                        acc[q][0] = fma2(p2, v0.x, acc[q][0]);
                        acc[q][1] = fma2(p2, v0.y, acc[q][1]);
                        acc[q][2] = fma2(p2, v1.x, acc[q][2]);
                        acc[q][3] = fma2(p2, v1.y, acc[q][3]);
                        acc[q][4] = fma2(p2, v2v.x, acc[q][4]);
                        acc[q][5] = fma2(p2, v2v.y, acc[q][5]);
                        acc[q][6] = fma2(p2, v3.x, acc[q][6]);
                        acc[q][7] = fma2(p2, v3.y, acc[q][7]);
                    }
                }
            }
            __syncthreads();
        }

        const int bt = bth >> 3, h = bth & 7;
        #pragma unroll
        for (int q = 0; q < QPT; ++q) {
            int n = qc * (128 * QPT) + q * 128 + tid;
            const float inv = 1.0f / l[q];
            float* op = Oc + ((size_t)((bt << 10) | n)) * 128 + h * 16;
            #pragma unroll
            for (int r = 0; r < 8; ++r) {
                float2 v = upk2(acc[q][r]);
                op[r * 2]     = v.x * inv;
                op[r * 2 + 1] = v.y * inv;
            }
        }
    }
}

// ============================================================================
extern "C" void kernel_launch(void* const* d_in, const int* in_sizes, int n_in,
                              void* d_out, int out_size) {
    const float* query = (const float*)d_in[0];
    const float* key   = (const float*)d_in[1];
    const float* value = (const float*)d_in[2];
    const float* Wq    = (const float*)d_in[3];
    const float* bq    = (const float*)d_in[4];
    const float* Wk    = (const float*)d_in[5];
    const float* bk    = (const float*)d_in[6];
    const float* Wv    = (const float*)d_in[7];
    const float* bv    = (const float*)d_in[8];
    const float* Wo    = (const float*)d_in[9];
    const float* bo    = (const float*)d_in[10];
    float* out = (float*)d_out;

    float *qh, *kh, *vh, *ao;
    unsigned int* ctr;
    cudaGetSymbolAddress((void**)&qh, g_qh);
    cudaGetSymbolAddress((void**)&kh, g_kh);
    cudaGetSymbolAddress((void**)&vh, g_vh);
    cudaGetSymbolAddress((void**)&ao, g_ao);
    cudaGetSymbolAddress((void**)&ctr, g_ctr);

    cudaMemsetAsync(ctr, 0, sizeof(unsigned int));

    gemm_qkv<<<dim3(192, 3), 256>>>(query, key, value,
                                    Wq, Wk, Wv, bq, bk, bv,
                                    qh, kh, vh);
    attn_kernel<<<592, 128>>>(qh, kh, vh, ao);
    gemm_o<<<192, 256>>>(ao, Wo, bo, out);
}

// round 6
// speedup vs baseline: 1.0819x; 1.0819x over previous
#include <cuda_runtime.h>
#include <cstdint>

// Problem constants
#define R_TOTAL 24576   // B*T*N = 2*12*1024
#define DMODEL  128
#define NKEYS   1024
#define NHEADS  8
#define NITEMS  768     // 192 heads x 4 query-chunks of 256

typedef unsigned long long u64;

// ---------- packed f32x2 helpers ----------
__device__ __forceinline__ u64 pk2(float x, float y) {
    u64 r; asm("mov.b64 %0, {%1,%2};" : "=l"(r) : "f"(x), "f"(y)); return r;
}
__device__ __forceinline__ float2 upk2(u64 v) {
    float2 r; asm("mov.b64 {%0,%1}, %2;" : "=f"(r.x), "=f"(r.y) : "l"(v)); return r;
}
__device__ __forceinline__ u64 fma2(u64 a, u64 b, u64 c) {
    u64 d; asm("fma.rn.f32x2 %0, %1, %2, %3;" : "=l"(d) : "l"(a), "l"(b), "l"(c)); return d;
}
__device__ __forceinline__ u64 mul2(u64 a, u64 b) {
    u64 d; asm("mul.rn.f32x2 %0, %1, %2;" : "=l"(d) : "l"(a), "l"(b)); return d;
}
__device__ __forceinline__ u64 add2(u64 a, u64 b) {
    u64 d; asm("add.rn.f32x2 %0, %1, %2;" : "=l"(d) : "l"(a), "l"(b)); return d;
}
__device__ __forceinline__ float ex2(float x) {
    float y; asm("ex2.approx.f32 %0, %1;" : "=f"(y) : "f"(x)); return y;
}
__device__ __forceinline__ void cp16(void* dst, const void* src) {
    uint32_t d = (uint32_t)__cvta_generic_to_shared(dst);
    asm volatile("cp.async.cg.shared.global [%0], [%1], 16;" :: "r"(d), "l"(src));
}
__device__ __forceinline__ void cp_commit() {
    asm volatile("cp.async.commit_group;");
}
template<int N> __device__ __forceinline__ void cp_wait() {
    asm volatile("cp.async.wait_group %0;" :: "n"(N));
}

// ---------- scratch (no cudaMalloc allowed) ----------
__device__ float g_qh[R_TOTAL * DMODEL];   // head-major (bt,h,n,hd)
__device__ float g_kh[R_TOTAL * DMODEL];
__device__ float g_vh[R_TOTAL * DMODEL];
__device__ float g_ao[R_TOTAL * DMODEL];   // attention out, row-major (r, d)
__device__ unsigned int g_ctr;             // work-queue counter

// ============================================================================
// GEMM core (round-4 proven version, NO register prefetch):
// out[r,j] = sum_c X[r,c]*W[j,c] + bias[j]; 128 rows/block, N=K=128
// ============================================================================
__device__ __forceinline__ void gemm_body(
    const float* __restrict__ X, const float* __restrict__ W,
    const float* __restrict__ bias, float* __restrict__ out,
    int row0, int headmajor)
{
    __shared__ float Xs[32][132];
    __shared__ float Ws[32][132];

    const int tid = threadIdx.x;
    const int ti  = tid >> 4;
    const int tj  = tid & 15;

    u64 acc[8][4];
    #pragma unroll
    for (int i = 0; i < 8; ++i)
        #pragma unroll
        for (int jp = 0; jp < 4; ++jp) acc[i][jp] = 0ull;

    for (int kk = 0; kk < 128; kk += 32) {
        #pragma unroll
        for (int it = 0; it < 4; ++it) {
            int idx = it * 256 + tid;
            int i   = idx >> 3;
            int c4  = idx & 7;
            float4 xv = *(const float4*)(X + (size_t)(row0 + i) * 128 + kk + c4 * 4);
            Xs[c4*4+0][i] = xv.x; Xs[c4*4+1][i] = xv.y;
            Xs[c4*4+2][i] = xv.z; Xs[c4*4+3][i] = xv.w;
            float4 wv = *(const float4*)(W + (size_t)i * 128 + kk + c4 * 4);
            Ws[c4*4+0][i] = wv.x; Ws[c4*4+1][i] = wv.y;
            Ws[c4*4+2][i] = wv.z; Ws[c4*4+3][i] = wv.w;
        }
        __syncthreads();

        #pragma unroll
        for (int c = 0; c < 32; ++c) {
            float4 a0 = *(const float4*)(&Xs[c][ti * 8]);
            float4 a1 = *(const float4*)(&Xs[c][ti * 8 + 4]);
            const ulonglong2* bp = (const ulonglong2*)(&Ws[c][tj * 8]);
            ulonglong2 bA = bp[0], bB = bp[1];
            u64 b2[4] = { bA.x, bA.y, bB.x, bB.y };
            float a[8] = {a0.x, a0.y, a0.z, a0.w, a1.x, a1.y, a1.z, a1.w};
            #pragma unroll
            for (int i = 0; i < 8; ++i) {
                u64 ad = pk2(a[i], a[i]);
                #pragma unroll
                for (int jp = 0; jp < 4; ++jp)
                    acc[i][jp] = fma2(ad, b2[jp], acc[i][jp]);
            }
        }
        __syncthreads();
    }

    #pragma unroll
    for (int i = 0; i < 8; ++i) {
        int r = row0 + ti * 8 + i;
        #pragma unroll
        for (int jp = 0; jp < 4; ++jp) {
            float2 v = upk2(acc[i][jp]);
            int j0 = tj * 8 + jp * 2;
            float o0 = v.x + bias[j0];
            float o1 = v.y + bias[j0 + 1];
            if (headmajor) {
                int bt = r >> 10, n = r & 1023;
                int h  = j0 >> 4, hd = j0 & 15;
                float* dst = out + (((size_t)(bt * NHEADS + h)) << 14) + (n << 4) + hd;
                dst[0] = o0; dst[1] = o1;
            } else {
                out[(size_t)r * 128 + j0]     = o0;
                out[(size_t)r * 128 + j0 + 1] = o1;
            }
        }
    }
}

__global__ __launch_bounds__(256) void gemm_qkv(
    const float* __restrict__ Xq, const float* __restrict__ Xk,
    const float* __restrict__ Xv,
    const float* __restrict__ Wq, const float* __restrict__ Wk,
    const float* __restrict__ Wv,
    const float* __restrict__ bq, const float* __restrict__ bk,
    const float* __restrict__ bv,
    float* __restrict__ oq, float* __restrict__ ok, float* __restrict__ ov)
{
    const int which = blockIdx.y;
    const float* X = (which == 0) ? Xq : (which == 1) ? Xk : Xv;
    const float* W = (which == 0) ? Wq : (which == 1) ? Wk : Wv;
    const float* b = (which == 0) ? bq : (which == 1) ? bk : bv;
    float*       o = (which == 0) ? oq : (which == 1) ? ok : ov;
    gemm_body(X, W, b, o, blockIdx.x * 128, 1);
}

__global__ __launch_bounds__(256) void gemm_o(
    const float* __restrict__ X, const float* __restrict__ W,
    const float* __restrict__ bias, float* __restrict__ out)
{
    gemm_body(X, W, bias, out, blockIdx.x * 128, 0);
}

// ============================================================================
// Attention v6: persistent CTAs + software-pipelined inner loop.
// K rows for iteration j+2 are loaded during iteration j's AV phase, hiding
// the 29-cyc LDS latency behind the 32-FMA2 AV block. l split even/odd.
// Grid 592, block 128, QPT=2 (256 q/item), K/V double-buffered 128-key tiles.
// ============================================================================
#define QPT 2
#define TK  128
#define NTILES (NKEYS / TK)

__global__ __launch_bounds__(128, 4) void attn_kernel(
    const float* __restrict__ Qh, const float* __restrict__ Kh,
    const float* __restrict__ Vh, float* __restrict__ Oc)
{
    __shared__ float Ks[2][TK * 16];   // 2 x 8 KB
    __shared__ float Vs[2][TK * 16];   // 2 x 8 KB
    __shared__ unsigned int sh_item;

    const int tid = threadIdx.x;
    const float sc = 0.25f * 1.4426950408889634f;   // (1/sqrt16)*log2(e)
    const u64 scale2 = pk2(sc, sc);

    for (;;) {
        if (tid == 0) sh_item = atomicAdd(&g_ctr, 1u);
        __syncthreads();
        const unsigned int item = sh_item;
        __syncthreads();
        if (item >= NITEMS) break;

        const int bth = item >> 2;          // 0..191
        const int qc  = item & 3;           // 0..3

        const float* Kg = Kh + (size_t)bth * 16384;
        const float* Vg = Vh + (size_t)bth * 16384;

        // prefetch tile 0
        #pragma unroll
        for (int i = 0; i < 4; ++i) {
            int idx = tid + i * 128;
            cp16(&Ks[0][idx * 4], Kg + idx * 4);
            cp16(&Vs[0][idx * 4], Vg + idx * 4);
        }
        cp_commit();

        // load + prescale queries
        u64 q2[QPT][8];
        #pragma unroll
        for (int q = 0; q < QPT; ++q) {
            int n = qc * (128 * QPT) + q * 128 + tid;
            const float* qp = Qh + (size_t)bth * 16384 + n * 16;
            #pragma unroll
            for (int r = 0; r < 4; ++r) {
                ulonglong2 qv = *(const ulonglong2*)(qp + r * 4);
                q2[q][r * 2]     = mul2(qv.x, scale2);
                q2[q][r * 2 + 1] = mul2(qv.y, scale2);
            }
        }

        u64 acc[QPT][8];
        #pragma unroll
        for (int q = 0; q < QPT; ++q)
            #pragma unroll
            for (int r = 0; r < 8; ++r) acc[q][r] = 0ull;
        float lA[QPT], lB[QPT];
        #pragma unroll
        for (int q = 0; q < QPT; ++q) { lA[q] = 0.0f; lB[q] = 0.0f; }

        #pragma unroll 1
        for (int t = 0; t < NTILES; ++t) {
            const int buf = t & 1;
            if (t < NTILES - 1) {
                const int nb = buf ^ 1;
                const float* kp = Kg + (t + 1) * TK * 16;
                const float* vp = Vg + (t + 1) * TK * 16;
                #pragma unroll
                for (int i = 0; i < 4; ++i) {
                    int idx = tid + i * 128;
                    cp16(&Ks[nb][idx * 4], kp + idx * 4);
                    cp16(&Vs[nb][idx * 4], vp + idx * 4);
                }
                cp_commit();
                cp_wait<1>();
            } else {
                cp_wait<0>();
            }
            __syncthreads();

            const float* Kt = Ks[buf];
            const float* Vt = Vs[buf];

            // preload K rows 0,1 into registers (pipeline prologue)
            u64 ka[8];
            {
                const ulonglong2* k0p = (const ulonglong2*)(Kt);
                const ulonglong2* k1p = (const ulonglong2*)(Kt + 16);
                ulonglong2 a0 = k0p[0], a1 = k0p[1];
                ulonglong2 b0 = k1p[0], b1 = k1p[1];
                ka[0] = a0.x; ka[1] = a0.y; ka[2] = a1.x; ka[3] = a1.y;
                ka[4] = b0.x; ka[5] = b0.y; ka[6] = b1.x; ka[7] = b1.y;
            }

            #pragma unroll 2
            for (int j = 0; j < TK; j += 2) {
                // --- phase 1: scores for keys j, j+1 from registers ---
                u64 sa[2][QPT], sb[2][QPT];
                #pragma unroll
                for (int kk = 0; kk < 2; ++kk) {
                    #pragma unroll
                    for (int q = 0; q < QPT; ++q) {
                        u64 a = mul2(q2[q][0], ka[kk * 4 + 0]);
                        u64 b = mul2(q2[q][2], ka[kk * 4 + 1]);
                        a = fma2(q2[q][4], ka[kk * 4 + 2], a);
                        b = fma2(q2[q][6], ka[kk * 4 + 3], b);
                        sa[kk][q] = a; sb[kk][q] = b;
                    }
                }
                // NOTE: q2 layout vs ka layout — ka[kk*4+r] = 4 floats (2 f32x2)
                // Each ka slot is hd pairs {4r..4r+3}; q2 index must match:
                // q2[q][0..7] are hd pairs {0,1},{2,3},... so pair r uses q2[q][2r],[2r+1].
                // Redo properly below (the above used stride-2 q2; correct it):
                #pragma unroll
                for (int kk = 0; kk < 2; ++kk) {
                    #pragma unroll
                    for (int q = 0; q < QPT; ++q) {
                        u64 a = mul2(q2[q][0], ka[kk * 4 + 0]);
                        u64 b = mul2(q2[q][1], ka[kk * 4 + 0]);
                        // placeholder replaced below
                        (void)a; (void)b;
                    }
                }
                // --- actual correct score computation ---
                #pragma unroll
                for (int kk = 0; kk < 2; ++kk) {
                    #pragma unroll
                    for (int q = 0; q < QPT; ++q) {
                        u64 a = mul2(q2[q][0], ka[kk * 4 + 0]);      // hd 0-1
                        u64 b = mul2(q2[q][1], ka[kk * 4 + 1]);      // hd 2-3... 
                        a = fma2(q2[q][2], ka[kk * 4 + 2], a);
                        b = fma2(q2[q][3], ka[kk * 4 + 3], b);
                        sa[kk][q] = a; sb[kk][q] = b;
                    }
                }
                // ka holds only 4 u64 = 8 floats per key (half a row)!  The row is
                // 16 floats = 8 u64.  Fix: second half read directly from smem here
                // (still overlapped well since first half came from registers).
                const ulonglong2* kj0 = (const ulonglong2*)(Kt + j * 16) + 2;
                const ulonglong2* kj1 = (const ulonglong2*)(Kt + (j + 1) * 16) + 2;
                ulonglong2 h0 = kj0[0], h1 = kj0[1];
                ulonglong2 h2 = kj1[0], h3 = kj1[1];
                #pragma unroll
                for (int q = 0; q < QPT; ++q) {
                    sa[0][q] = fma2(q2[q][4], h0.x, sa[0][q]);
                    sb[0][q] = fma2(q2[q][5], h0.y, sb[0][q]);
                    sa[0][q] = fma2(q2[q][6], h1.x, sa[0][q]);
                    sb[0][q] = fma2(q2[q][7], h1.y, sb[0][q]);
                    sa[1][q] = fma2(q2[q][4], h2.x, sa[1][q]);
                    sb[1][q] = fma2(q2[q][5], h2.y, sb[1][q]);
                    sa[1][q] = fma2(q2[q][6], h3.x, sa[1][q]);
                    sb[1][q] = fma2(q2[q][7], h3.y, sb[1][q]);
                }

                // --- prefetch next pair's FIRST-half K rows into ka ---
                if (j + 2 < TK) {
                    const ulonglong2* n0 = (const ulonglong2*)(Kt + (j + 2) * 16);
                    const ulonglong2* n1 = (const ulonglong2*)(Kt + (j + 3) * 16);
                    ulonglong2 a0 = n0[0], a1 = n0[1];
                    ulonglong2 b0 = n1[0], b1 = n1[1];
                    ka[0] = a0.x; ka[1] = a0.y; ka[2] = a1.x; ka[3] = a1.y;
                    ka[4] = b0.x; ka[5] = b0.y; ka[6] = b1.x; ka[7] = b1.y;
                }

                // --- phase 2: reduce + exp ---
                float p[2][QPT];
                #pragma unroll
                for (int kk = 0; kk < 2; ++kk)
                    #pragma unroll
                    for (int q = 0; q < QPT; ++q) {
                        float2 f = upk2(add2(sa[kk][q], sb[kk][q]));
                        p[kk][q] = ex2(f.x + f.y);
                    }
                #pragma unroll
                for (int q = 0; q < QPT; ++q) {
                    lA[q] += p[0][q];
                    lB[q] += p[1][q];
                }

                // --- phase 3: V accumulate (LDS here overlaps nothing critical;
                //     next iteration's scores use the prefetched ka) ---
                #pragma unroll
                for (int kk = 0; kk < 2; ++kk) {
                    const ulonglong2* vj = (const ulonglong2*)(Vt + (j + kk) * 16);
                    ulonglong2 v0 = vj[0], v1 = vj[1], v2v = vj[2], v3 = vj[3];
                    #pragma unroll
                    for (int q = 0; q < QPT; ++q) {
                        u64 p2 = pk2(p[kk][q], p[kk][q]);
                        acc[q][0] = fma2(p2, v0.x, acc[q][0]);
                        acc[q][1] = fma2(p2, v0.y, acc[q][1]);
                        acc[q][2] = fma2(p2, v1.x, acc[q][2]);
                        acc[q][3] = fma2(p2, v1.y, acc[q][3]);
                        acc[q][4] = fma2(p2, v2v.x, acc[q][4]);
                        acc[q][5] = fma2(p2, v2v.y, acc[q][5]);
                        acc[q][6] = fma2(p2, v3.x, acc[q][6]);
                        acc[q][7] = fma2(p2, v3.y, acc[q][7]);
                    }
                }
            }
            __syncthreads();
        }

        const int bt = bth >> 3, h = bth & 7;
        #pragma unroll
        for (int q = 0; q < QPT; ++q) {
            int n = qc * (128 * QPT) + q * 128 + tid;
            const float inv = 1.0f / (lA[q] + lB[q]);
            float* op = Oc + ((size_t)((bt << 10) | n)) * 128 + h * 16;
            #pragma unroll
            for (int r = 0; r < 8; ++r) {
                float2 v = upk2(acc[q][r]);
                op[r * 2]     = v.x * inv;
                op[r * 2 + 1] = v.y * inv;
            }
        }
    }
}

// ============================================================================
extern "C" void kernel_launch(void* const* d_in, const int* in_sizes, int n_in,
                              void* d_out, int out_size) {
    const float* query = (const float*)d_in[0];
    const float* key   = (const float*)d_in[1];
    const float* value = (const float*)d_in[2];
    const float* Wq    = (const float*)d_in[3];
    const float* bq    = (const float*)d_in[4];
    const float* Wk    = (const float*)d_in[5];
    const float* bk    = (const float*)d_in[6];
    const float* Wv    = (const float*)d_in[7];
    const float* bv    = (const float*)d_in[8];
    const float* Wo    = (const float*)d_in[9];
    const float* bo    = (const float*)d_in[10];
    float* out = (float*)d_out;

    float *qh, *kh, *vh, *ao;
    unsigned int* ctr;
    cudaGetSymbolAddress((void**)&qh, g_qh);
    cudaGetSymbolAddress((void**)&kh, g_kh);
    cudaGetSymbolAddress((void**)&vh, g_vh);
    cudaGetSymbolAddress((void**)&ao, g_ao);
    cudaGetSymbolAddress((void**)&ctr, g_ctr);

    cudaMemsetAsync(ctr, 0, sizeof(unsigned int));

    gemm_qkv<<<dim3(192, 3), 256>>>(query, key, value,
                                    Wq, Wk, Wv, bq, bk, bv,
                                    qh, kh, vh);
    attn_kernel<<<592, 128>>>(qh, kh, vh, ao);
    gemm_o<<<192, 256>>>(ao, Wo, bo, out);
}

// round 8
// speedup vs baseline: 1.3215x; 1.2215x over previous
#include <cuda_runtime.h>
#include <cuda_bf16.h>
#include <cstdint>

// Problem constants
#define R_TOTAL 24576   // B*T*N = 2*12*1024
#define DMODEL  128
#define NKEYS   1024
#define NHEADS  8
#define NITEMS  768     // 192 heads x 4 query-chunks of 256

typedef unsigned long long u64;

// ---------- packed f32x2 helpers ----------
__device__ __forceinline__ u64 pk2(float x, float y) {
    u64 r; asm("mov.b64 %0, {%1,%2};" : "=l"(r) : "f"(x), "f"(y)); return r;
}
__device__ __forceinline__ float2 upk2(u64 v) {
    float2 r; asm("mov.b64 {%0,%1}, %2;" : "=f"(r.x), "=f"(r.y) : "l"(v)); return r;
}
__device__ __forceinline__ u64 fma2(u64 a, u64 b, u64 c) {
    u64 d; asm("fma.rn.f32x2 %0, %1, %2, %3;" : "=l"(d) : "l"(a), "l"(b), "l"(c)); return d;
}
__device__ __forceinline__ u64 mul2(u64 a, u64 b) {
    u64 d; asm("mul.rn.f32x2 %0, %1, %2;" : "=l"(d) : "l"(a), "l"(b)); return d;
}
__device__ __forceinline__ u64 add2(u64 a, u64 b) {
    u64 d; asm("add.rn.f32x2 %0, %1, %2;" : "=l"(d) : "l"(a), "l"(b)); return d;
}
__device__ __forceinline__ float ex2(float x) {
    float y; asm("ex2.approx.f32 %0, %1;" : "=f"(y) : "f"(x)); return y;
}
__device__ __forceinline__ void cp16(void* dst, const void* src) {
    uint32_t d = (uint32_t)__cvta_generic_to_shared(dst);
    asm volatile("cp.async.cg.shared.global [%0], [%1], 16;" :: "r"(d), "l"(src));
}
__device__ __forceinline__ void cp_commit() {
    asm volatile("cp.async.commit_group;");
}
template<int N> __device__ __forceinline__ void cp_wait() {
    asm volatile("cp.async.wait_group %0;" :: "n"(N));
}

// ---------- HMMA: mma.sync m16n8k16 bf16 (baseline PTX, works on sm_103) ----
__device__ __forceinline__ void mma_bf16(float* c, const uint32_t* a,
                                         uint32_t b0, uint32_t b1) {
    asm volatile(
        "mma.sync.aligned.m16n8k16.row.col.f32.bf16.bf16.f32 "
        "{%0,%1,%2,%3}, {%4,%5,%6,%7}, {%8,%9}, {%0,%1,%2,%3};"
        : "+f"(c[0]), "+f"(c[1]), "+f"(c[2]), "+f"(c[3])
        : "r"(a[0]), "r"(a[1]), "r"(a[2]), "r"(a[3]), "r"(b0), "r"(b1));
}

// split fp32 -> (hi, lo) bf16 pair
__device__ __forceinline__ void bsplit(float x, unsigned short& h, unsigned short& l) {
    __nv_bfloat16 bh = __float2bfloat16(x);
    __nv_bfloat16 bl = __float2bfloat16(x - __bfloat162float(bh));
    h = __bfloat16_as_ushort(bh);
    l = __bfloat16_as_ushort(bl);
}

// ---------- scratch (no cudaMalloc allowed) ----------
__device__ float g_qh[R_TOTAL * DMODEL];   // head-major (bt,h,n,hd)
__device__ float g_kh[R_TOTAL * DMODEL];
__device__ float g_vh[R_TOTAL * DMODEL];
__device__ float g_ao[R_TOTAL * DMODEL];   // attention out, row-major (r, d)
__device__ unsigned int g_ctr;             // work-queue counter

// ============================================================================
// HMMA GEMM: out[r,j] = sum_c X[r,c]*W[j,c] + bias[j]
// 128x128 tile/CTA, K=128 in 32-chunks. Split-bf16 (3 mma terms, fp32 accum).
// 8 warps in 4(m) x 2(n) layout, warp tile 32x64.
// Smem rows padded to 20 words (40 bf16) -> conflict-free fragment LDS.
// ============================================================================
#define SPAD 20   // words per smem row

__device__ __forceinline__ void gemm_hmma_body(
    const float* __restrict__ X, const float* __restrict__ W,
    const float* __restrict__ bias, float* __restrict__ out,
    int row0, int headmajor)
{
    __shared__ uint32_t XsHi[128 * SPAD], XsLo[128 * SPAD];
    __shared__ uint32_t WsHi[128 * SPAD], WsLo[128 * SPAD];

    const int tid   = threadIdx.x;
    const int wid   = tid >> 5;
    const int lane  = tid & 31;
    const int g     = lane >> 2;       // group 0..7
    const int t     = lane & 3;        // thread-in-group
    const int mwarp = wid & 3;         // 4 m-groups of 32 rows
    const int nwarp = wid >> 2;        // 2 n-groups of 64 cols

    float c[2][8][4];
    #pragma unroll
    for (int mt = 0; mt < 2; ++mt)
        #pragma unroll
        for (int nt = 0; nt < 8; ++nt)
            #pragma unroll
            for (int e = 0; e < 4; ++e) c[mt][nt][e] = 0.0f;

    for (int chunk = 0; chunk < 4; ++chunk) {
        const int k0 = chunk * 32;
        // ---- stage X and W chunks (fp32 -> hi/lo bf16) ----
        #pragma unroll
        for (int i = 0; i < 4; ++i) {
            int idx = tid + i * 256;          // 0..1023
            int row = idx >> 3;               // 0..127
            int c4  = idx & 7;                // float4 slot in 32-col chunk
            float4 v = *(const float4*)(X + (size_t)(row0 + row) * 128 + k0 + c4 * 4);
            unsigned short h0, l0, h1, l1, h2, l2, h3, l3;
            bsplit(v.x, h0, l0); bsplit(v.y, h1, l1);
            bsplit(v.z, h2, l2); bsplit(v.w, h3, l3);
            int wi = row * SPAD + c4 * 2;
            XsHi[wi]     = (uint32_t)h0 | ((uint32_t)h1 << 16);
            XsHi[wi + 1] = (uint32_t)h2 | ((uint32_t)h3 << 16);
            XsLo[wi]     = (uint32_t)l0 | ((uint32_t)l1 << 16);
            XsLo[wi + 1] = (uint32_t)l2 | ((uint32_t)l3 << 16);

            float4 wv = *(const float4*)(W + (size_t)row * 128 + k0 + c4 * 4);
            bsplit(wv.x, h0, l0); bsplit(wv.y, h1, l1);
            bsplit(wv.z, h2, l2); bsplit(wv.w, h3, l3);
            WsHi[wi]     = (uint32_t)h0 | ((uint32_t)h1 << 16);
            WsHi[wi + 1] = (uint32_t)h2 | ((uint32_t)h3 << 16);
            WsLo[wi]     = (uint32_t)l0 | ((uint32_t)l1 << 16);
            WsLo[wi + 1] = (uint32_t)l2 | ((uint32_t)l3 << 16);
        }
        __syncthreads();

        // ---- 2 k16-steps per chunk ----
        #pragma unroll
        for (int ks = 0; ks < 2; ++ks) {
            const int kw = ks * 8;                 // word offset of this k-step
            uint32_t ahi[2][4], alo[2][4];
            #pragma unroll
            for (int mt = 0; mt < 2; ++mt) {
                int r0 = (mwarp * 32 + mt * 16 + g) * SPAD + kw + t;
                int r8 = r0 + 8 * SPAD;
                ahi[mt][0] = XsHi[r0];     ahi[mt][1] = XsHi[r8];
                ahi[mt][2] = XsHi[r0 + 4]; ahi[mt][3] = XsHi[r8 + 4];
                alo[mt][0] = XsLo[r0];     alo[mt][1] = XsLo[r8];
                alo[mt][2] = XsLo[r0 + 4]; alo[mt][3] = XsLo[r8 + 4];
            }
            #pragma unroll
            for (int nt = 0; nt < 8; ++nt) {
                int b = (nwarp * 64 + nt * 8 + g) * SPAD + kw + t;
                uint32_t bh0 = WsHi[b], bh1 = WsHi[b + 4];
                uint32_t bl0 = WsLo[b], bl1 = WsLo[b + 4];
                #pragma unroll
                for (int mt = 0; mt < 2; ++mt) {
                    mma_bf16(c[mt][nt], ahi[mt], bh0, bh1);
                    mma_bf16(c[mt][nt], ahi[mt], bl0, bl1);
                    mma_bf16(c[mt][nt], alo[mt], bh0, bh1);
                }
            }
        }
        __syncthreads();
    }

    // ---- epilogue: write C + bias ----
    #pragma unroll
    for (int mt = 0; mt < 2; ++mt) {
        int rA = row0 + mwarp * 32 + mt * 16 + g;
        int rB = rA + 8;
        #pragma unroll
        for (int nt = 0; nt < 8; ++nt) {
            int j0 = nwarp * 64 + nt * 8 + t * 2;
            float b0 = bias[j0], b1 = bias[j0 + 1];
            float2 oA = { c[mt][nt][0] + b0, c[mt][nt][1] + b1 };
            float2 oB = { c[mt][nt][2] + b0, c[mt][nt][3] + b1 };
            if (headmajor) {
                int h = j0 >> 4, hd = j0 & 15;
                int btA = rA >> 10, nA = rA & 1023;
                int btB = rB >> 10, nB = rB & 1023;
                *(float2*)(out + (((size_t)(btA * NHEADS + h)) << 14) + (nA << 4) + hd) = oA;
                *(float2*)(out + (((size_t)(btB * NHEADS + h)) << 14) + (nB << 4) + hd) = oB;
            } else {
                *(float2*)(out + (size_t)rA * 128 + j0) = oA;
                *(float2*)(out + (size_t)rB * 128 + j0) = oB;
            }
        }
    }
}

__global__ __launch_bounds__(256, 2) void gemm_qkv(
    const float* __restrict__ Xq, const float* __restrict__ Xk,
    const float* __restrict__ Xv,
    const float* __restrict__ Wq, const float* __restrict__ Wk,
    const float* __restrict__ Wv,
    const float* __restrict__ bq, const float* __restrict__ bk,
    const float* __restrict__ bv,
    float* __restrict__ oq, float* __restrict__ ok, float* __restrict__ ov)
{
    const int which = blockIdx.y;
    const float* X = (which == 0) ? Xq : (which == 1) ? Xk : Xv;
    const float* W = (which == 0) ? Wq : (which == 1) ? Wk : Wv;
    const float* b = (which == 0) ? bq : (which == 1) ? bk : bv;
    float*       o = (which == 0) ? oq : (which == 1) ? ok : ov;
    gemm_hmma_body(X, W, b, o, blockIdx.x * 128, 1);
}

__global__ __launch_bounds__(256, 2) void gemm_o(
    const float* __restrict__ X, const float* __restrict__ W,
    const float* __restrict__ bias, float* __restrict__ out)
{
    gemm_hmma_body(X, W, bias, out, blockIdx.x * 128, 0);
}

// ============================================================================
// Attention v6 (unchanged): persistent CTAs, software-pipelined inner loop,
// double-buffered 128-key K/V tiles.
// ============================================================================
#define QPT 2
#define TK  128
#define NTILES (NKEYS / TK)

__global__ __launch_bounds__(128, 4) void attn_kernel(
    const float* __restrict__ Qh, const float* __restrict__ Kh,
    const float* __restrict__ Vh, float* __restrict__ Oc)
{
    __shared__ float Ks[2][TK * 16];
    __shared__ float Vs[2][TK * 16];
    __shared__ unsigned int sh_item;

    const int tid = threadIdx.x;
    const float sc = 0.25f * 1.4426950408889634f;
    const u64 scale2 = pk2(sc, sc);

    for (;;) {
        if (tid == 0) sh_item = atomicAdd(&g_ctr, 1u);
        __syncthreads();
        const unsigned int item = sh_item;
        __syncthreads();
        if (item >= NITEMS) break;

        const int bth = item >> 2;
        const int qc  = item & 3;

        const float* Kg = Kh + (size_t)bth * 16384;
        const float* Vg = Vh + (size_t)bth * 16384;

        #pragma unroll
        for (int i = 0; i < 4; ++i) {
            int idx = tid + i * 128;
            cp16(&Ks[0][idx * 4], Kg + idx * 4);
            cp16(&Vs[0][idx * 4], Vg + idx * 4);
        }
        cp_commit();

        u64 q2[QPT][8];
        #pragma unroll
        for (int q = 0; q < QPT; ++q) {
            int n = qc * (128 * QPT) + q * 128 + tid;
            const float* qp = Qh + (size_t)bth * 16384 + n * 16;
            #pragma unroll
            for (int r = 0; r < 4; ++r) {
                ulonglong2 qv = *(const ulonglong2*)(qp + r * 4);
                q2[q][r * 2]     = mul2(qv.x, scale2);
                q2[q][r * 2 + 1] = mul2(qv.y, scale2);
            }
        }

        u64 acc[QPT][8];
        #pragma unroll
        for (int q = 0; q < QPT; ++q)
            #pragma unroll
            for (int r = 0; r < 8; ++r) acc[q][r] = 0ull;
        float lA[QPT], lB[QPT];
        #pragma unroll
        for (int q = 0; q < QPT; ++q) { lA[q] = 0.0f; lB[q] = 0.0f; }

        #pragma unroll 1
        for (int tt = 0; tt < NTILES; ++tt) {
            const int buf = tt & 1;
            if (tt < NTILES - 1) {
                const int nb = buf ^ 1;
                const float* kp = Kg + (tt + 1) * TK * 16;
                const float* vp = Vg + (tt + 1) * TK * 16;
                #pragma unroll
                for (int i = 0; i < 4; ++i) {
                    int idx = tid + i * 128;
                    cp16(&Ks[nb][idx * 4], kp + idx * 4);
                    cp16(&Vs[nb][idx * 4], vp + idx * 4);
                }
                cp_commit();
                cp_wait<1>();
            } else {
                cp_wait<0>();
            }
            __syncthreads();

            const float* Kt = Ks[buf];
            const float* Vt = Vs[buf];

            u64 ka[8];
            {
                const ulonglong2* k0p = (const ulonglong2*)(Kt);
                const ulonglong2* k1p = (const ulonglong2*)(Kt + 16);
                ulonglong2 a0 = k0p[0], a1 = k0p[1];
                ulonglong2 b0 = k1p[0], b1 = k1p[1];
                ka[0] = a0.x; ka[1] = a0.y; ka[2] = a1.x; ka[3] = a1.y;
                ka[4] = b0.x; ka[5] = b0.y; ka[6] = b1.x; ka[7] = b1.y;
            }

            #pragma unroll 2
            for (int j = 0; j < TK; j += 2) {
                u64 sa[2][QPT], sb2[2][QPT];
                #pragma unroll
                for (int kk = 0; kk < 2; ++kk) {
                    #pragma unroll
                    for (int q = 0; q < QPT; ++q) {
                        u64 a = mul2(q2[q][0], ka[kk * 4 + 0]);
                        u64 b = mul2(q2[q][1], ka[kk * 4 + 1]);
                        a = fma2(q2[q][2], ka[kk * 4 + 2], a);
                        b = fma2(q2[q][3], ka[kk * 4 + 3], b);
                        sa[kk][q] = a; sb2[kk][q] = b;
                    }
                }
                const ulonglong2* kj0 = (const ulonglong2*)(Kt + j * 16) + 2;
                const ulonglong2* kj1 = (const ulonglong2*)(Kt + (j + 1) * 16) + 2;
                ulonglong2 h0 = kj0[0], h1 = kj0[1];
                ulonglong2 h2 = kj1[0], h3 = kj1[1];
                #pragma unroll
                for (int q = 0; q < QPT; ++q) {
                    sa[0][q] = fma2(q2[q][4], h0.x, sa[0][q]);
                    sb2[0][q] = fma2(q2[q][5], h0.y, sb2[0][q]);
                    sa[0][q] = fma2(q2[q][6], h1.x, sa[0][q]);
                    sb2[0][q] = fma2(q2[q][7], h1.y, sb2[0][q]);
                    sa[1][q] = fma2(q2[q][4], h2.x, sa[1][q]);
                    sb2[1][q] = fma2(q2[q][5], h2.y, sb2[1][q]);
                    sa[1][q] = fma2(q2[q][6], h3.x, sa[1][q]);
                    sb2[1][q] = fma2(q2[q][7], h3.y, sb2[1][q]);
                }

                if (j + 2 < TK) {
                    const ulonglong2* n0 = (const ulonglong2*)(Kt + (j + 2) * 16);
                    const ulonglong2* n1 = (const ulonglong2*)(Kt + (j + 3) * 16);
                    ulonglong2 a0 = n0[0], a1 = n0[1];
                    ulonglong2 b0 = n1[0], b1 = n1[1];
                    ka[0] = a0.x; ka[1] = a0.y; ka[2] = a1.x; ka[3] = a1.y;
                    ka[4] = b0.x; ka[5] = b0.y; ka[6] = b1.x; ka[7] = b1.y;
                }

                float p[2][QPT];
                #pragma unroll
                for (int kk = 0; kk < 2; ++kk)
                    #pragma unroll
                    for (int q = 0; q < QPT; ++q) {
                        float2 f = upk2(add2(sa[kk][q], sb2[kk][q]));
                        p[kk][q] = ex2(f.x + f.y);
                    }
                #pragma unroll
                for (int q = 0; q < QPT; ++q) {
                    lA[q] += p[0][q];
                    lB[q] += p[1][q];
                }

                #pragma unroll
                for (int kk = 0; kk < 2; ++kk) {
                    const ulonglong2* vj = (const ulonglong2*)(Vt + (j + kk) * 16);
                    ulonglong2 v0 = vj[0], v1 = vj[1], v2v = vj[2], v3 = vj[3];
                    #pragma unroll
                    for (int q = 0; q < QPT; ++q) {
                        u64 p2 = pk2(p[kk][q], p[kk][q]);
                        acc[q][0] = fma2(p2, v0.x, acc[q][0]);
                        acc[q][1] = fma2(p2, v0.y, acc[q][1]);
                        acc[q][2] = fma2(p2, v1.x, acc[q][2]);
                        acc[q][3] = fma2(p2, v1.y, acc[q][3]);
                        acc[q][4] = fma2(p2, v2v.x, acc[q][4]);
                        acc[q][5] = fma2(p2, v2v.y, acc[q][5]);
                        acc[q][6] = fma2(p2, v3.x, acc[q][6]);
                        acc[q][7] = fma2(p2, v3.y, acc[q][7]);
                    }
                }
            }
            __syncthreads();
        }

        const int bt = bth >> 3, h = bth & 7;
        #pragma unroll
        for (int q = 0; q < QPT; ++q) {
            int n = qc * (128 * QPT) + q * 128 + tid;
            const float inv = 1.0f / (lA[q] + lB[q]);
            float* op = Oc + ((size_t)((bt << 10) | n)) * 128 + h * 16;
            #pragma unroll
            for (int r = 0; r < 8; ++r) {
                float2 v = upk2(acc[q][r]);
                op[r * 2]     = v.x * inv;
                op[r * 2 + 1] = v.y * inv;
            }
        }
    }
}

// ============================================================================
extern "C" void kernel_launch(void* const* d_in, const int* in_sizes, int n_in,
                              void* d_out, int out_size) {
    const float* query = (const float*)d_in[0];
    const float* key   = (const float*)d_in[1];
    const float* value = (const float*)d_in[2];
    const float* Wq    = (const float*)d_in[3];
    const float* bq    = (const float*)d_in[4];
    const float* Wk    = (const float*)d_in[5];
    const float* bk    = (const float*)d_in[6];
    const float* Wv    = (const float*)d_in[7];
    const float* bv    = (const float*)d_in[8];
    const float* Wo    = (const float*)d_in[9];
    const float* bo    = (const float*)d_in[10];
    float* out = (float*)d_out;

    float *qh, *kh, *vh, *ao;
    unsigned int* ctr;
    cudaGetSymbolAddress((void**)&qh, g_qh);
    cudaGetSymbolAddress((void**)&kh, g_kh);
    cudaGetSymbolAddress((void**)&vh, g_vh);
    cudaGetSymbolAddress((void**)&ao, g_ao);
    cudaGetSymbolAddress((void**)&ctr, g_ctr);

    cudaMemsetAsync(ctr, 0, sizeof(unsigned int));

    gemm_qkv<<<dim3(192, 3), 256>>>(query, key, value,
                                    Wq, Wk, Wv, bq, bk, bv,
                                    qh, kh, vh);
    attn_kernel<<<592, 128>>>(qh, kh, vh, ao);
    gemm_o<<<192, 256>>>(ao, Wo, bo, out);
}

// round 10
// speedup vs baseline: 2.6280x; 1.9886x over previous
#include <cuda_runtime.h>
#include <cuda_bf16.h>
#include <cstdint>

// Problem constants
#define R_TOTAL 24576   // B*T*N = 2*12*1024
#define DMODEL  128
#define NKEYS   1024
#define NHEADS  8

typedef unsigned long long u64;

// ---------- helpers ----------
__device__ __forceinline__ float ex2(float x) {
    float y; asm("ex2.approx.f32 %0, %1;" : "=f"(y) : "f"(x)); return y;
}
// pack two floats to bf16x2: low half = lo, high half = hi
__device__ __forceinline__ uint32_t pkbf(float lo, float hi) {
    uint32_t d;
    asm("cvt.rn.bf16x2.f32 %0, %1, %2;" : "=r"(d) : "f"(hi), "f"(lo));
    return d;
}

// HMMA: mma.sync m16n8k16 bf16 (baseline PTX, works on sm_103)
__device__ __forceinline__ void mma_bf16(float* c, const uint32_t* a,
                                         uint32_t b0, uint32_t b1) {
    asm volatile(
        "mma.sync.aligned.m16n8k16.row.col.f32.bf16.bf16.f32 "
        "{%0,%1,%2,%3}, {%4,%5,%6,%7}, {%8,%9}, {%0,%1,%2,%3};"
        : "+f"(c[0]), "+f"(c[1]), "+f"(c[2]), "+f"(c[3])
        : "r"(a[0]), "r"(a[1]), "r"(a[2]), "r"(a[3]), "r"(b0), "r"(b1));
}

// split fp32 -> (hi, lo) bf16 pair
__device__ __forceinline__ void bsplit(float x, unsigned short& h, unsigned short& l) {
    __nv_bfloat16 bh = __float2bfloat16(x);
    __nv_bfloat16 bl = __float2bfloat16(x - __bfloat162float(bh));
    h = __bfloat16_as_ushort(bh);
    l = __bfloat16_as_ushort(bl);
}

// split a packed-pair of floats into hi word + lo word
__device__ __forceinline__ void psplit(float p0, float p1, uint32_t& hw, uint32_t& lw) {
    hw = pkbf(p0, p1);
    float f0 = __uint_as_float(hw << 16);
    float f1 = __uint_as_float(hw & 0xffff0000u);
    lw = pkbf(p0 - f0, p1 - f1);
}

// ---------- scratch (no cudaMalloc allowed) ----------
__device__ float g_qh[R_TOTAL * DMODEL];   // head-major (bt,h,n,hd)
__device__ float g_kh[R_TOTAL * DMODEL];
__device__ float g_vh[R_TOTAL * DMODEL];
__device__ float g_ao[R_TOTAL * DMODEL];   // attention out, row-major (r, d)

// ============================================================================
// HMMA projection GEMM (round-8, proven): out[r,j] = X[r,:]·W[j,:] + bias[j]
// ============================================================================
#define SPAD 20

__device__ __forceinline__ void gemm_hmma_body(
    const float* __restrict__ X, const float* __restrict__ W,
    const float* __restrict__ bias, float* __restrict__ out,
    int row0, int headmajor)
{
    __shared__ uint32_t XsHi[128 * SPAD], XsLo[128 * SPAD];
    __shared__ uint32_t WsHi[128 * SPAD], WsLo[128 * SPAD];

    const int tid   = threadIdx.x;
    const int wid   = tid >> 5;
    const int lane  = tid & 31;
    const int g     = lane >> 2;
    const int t     = lane & 3;
    const int mwarp = wid & 3;
    const int nwarp = wid >> 2;

    float c[2][8][4];
    #pragma unroll
    for (int mt = 0; mt < 2; ++mt)
        #pragma unroll
        for (int nt = 0; nt < 8; ++nt)
            #pragma unroll
            for (int e = 0; e < 4; ++e) c[mt][nt][e] = 0.0f;

    for (int chunk = 0; chunk < 4; ++chunk) {
        const int k0 = chunk * 32;
        #pragma unroll
        for (int i = 0; i < 4; ++i) {
            int idx = tid + i * 256;
            int row = idx >> 3;
            int c4  = idx & 7;
            float4 v = *(const float4*)(X + (size_t)(row0 + row) * 128 + k0 + c4 * 4);
            unsigned short h0, l0, h1, l1, h2, l2, h3, l3;
            bsplit(v.x, h0, l0); bsplit(v.y, h1, l1);
            bsplit(v.z, h2, l2); bsplit(v.w, h3, l3);
            int wi = row * SPAD + c4 * 2;
            XsHi[wi]     = (uint32_t)h0 | ((uint32_t)h1 << 16);
            XsHi[wi + 1] = (uint32_t)h2 | ((uint32_t)h3 << 16);
            XsLo[wi]     = (uint32_t)l0 | ((uint32_t)l1 << 16);
            XsLo[wi + 1] = (uint32_t)l2 | ((uint32_t)l3 << 16);

            float4 wv = *(const float4*)(W + (size_t)row * 128 + k0 + c4 * 4);
            bsplit(wv.x, h0, l0); bsplit(wv.y, h1, l1);
            bsplit(wv.z, h2, l2); bsplit(wv.w, h3, l3);
            WsHi[wi]     = (uint32_t)h0 | ((uint32_t)h1 << 16);
            WsHi[wi + 1] = (uint32_t)h2 | ((uint32_t)h3 << 16);
            WsLo[wi]     = (uint32_t)l0 | ((uint32_t)l1 << 16);
            WsLo[wi + 1] = (uint32_t)l2 | ((uint32_t)l3 << 16);
        }
        __syncthreads();

        #pragma unroll
        for (int ks = 0; ks < 2; ++ks) {
            const int kw = ks * 8;
            uint32_t ahi[2][4], alo[2][4];
            #pragma unroll
            for (int mt = 0; mt < 2; ++mt) {
                int r0 = (mwarp * 32 + mt * 16 + g) * SPAD + kw + t;
                int r8 = r0 + 8 * SPAD;
                ahi[mt][0] = XsHi[r0];     ahi[mt][1] = XsHi[r8];
                ahi[mt][2] = XsHi[r0 + 4]; ahi[mt][3] = XsHi[r8 + 4];
                alo[mt][0] = XsLo[r0];     alo[mt][1] = XsLo[r8];
                alo[mt][2] = XsLo[r0 + 4]; alo[mt][3] = XsLo[r8 + 4];
            }
            #pragma unroll
            for (int nt = 0; nt < 8; ++nt) {
                int b = (nwarp * 64 + nt * 8 + g) * SPAD + kw + t;
                uint32_t bh0 = WsHi[b], bh1 = WsHi[b + 4];
                uint32_t bl0 = WsLo[b], bl1 = WsLo[b + 4];
                #pragma unroll
                for (int mt = 0; mt < 2; ++mt) {
                    mma_bf16(c[mt][nt], ahi[mt], bh0, bh1);
                    mma_bf16(c[mt][nt], ahi[mt], bl0, bl1);
                    mma_bf16(c[mt][nt], alo[mt], bh0, bh1);
                }
            }
        }
        __syncthreads();
    }

    #pragma unroll
    for (int mt = 0; mt < 2; ++mt) {
        int rA = row0 + mwarp * 32 + mt * 16 + g;
        int rB = rA + 8;
        #pragma unroll
        for (int nt = 0; nt < 8; ++nt) {
            int j0 = nwarp * 64 + nt * 8 + t * 2;
            float b0 = bias[j0], b1 = bias[j0 + 1];
            float2 oA = { c[mt][nt][0] + b0, c[mt][nt][1] + b1 };
            float2 oB = { c[mt][nt][2] + b0, c[mt][nt][3] + b1 };
            if (headmajor) {
                int h = j0 >> 4, hd = j0 & 15;
                int btA = rA >> 10, nA = rA & 1023;
                int btB = rB >> 10, nB = rB & 1023;
                *(float2*)(out + (((size_t)(btA * NHEADS + h)) << 14) + (nA << 4) + hd) = oA;
                *(float2*)(out + (((size_t)(btB * NHEADS + h)) << 14) + (nB << 4) + hd) = oB;
            } else {
                *(float2*)(out + (size_t)rA * 128 + j0) = oA;
                *(float2*)(out + (size_t)rB * 128 + j0) = oB;
            }
        }
    }
}

__global__ __launch_bounds__(256, 2) void gemm_qkv(
    const float* __restrict__ Xq, const float* __restrict__ Xk,
    const float* __restrict__ Xv,
    const float* __restrict__ Wq, const float* __restrict__ Wk,
    const float* __restrict__ Wv,
    const float* __restrict__ bq, const float* __restrict__ bk,
    const float* __restrict__ bv,
    float* __restrict__ oq, float* __restrict__ ok, float* __restrict__ ov)
{
    const int which = blockIdx.y;
    const float* X = (which == 0) ? Xq : (which == 1) ? Xk : Xv;
    const float* W = (which == 0) ? Wq : (which == 1) ? Wk : Wv;
    const float* b = (which == 0) ? bq : (which == 1) ? bk : bv;
    float*       o = (which == 0) ? oq : (which == 1) ? ok : ov;
    gemm_hmma_body(X, W, b, o, blockIdx.x * 128, 1);
}

__global__ __launch_bounds__(256, 2) void gemm_o(
    const float* __restrict__ X, const float* __restrict__ W,
    const float* __restrict__ bias, float* __restrict__ out)
{
    gemm_hmma_body(X, W, bias, out, blockIdx.x * 128, 0);
}

// ============================================================================
// Attention v7: HMMA flash-attention.
// Grid (8, 192): blockIdx.x = 128-query tile, blockIdx.y = bth.
// CTA 256 thr / 8 warps; warp owns 16 query rows; S fragments in registers;
// P converted in-register to A-fragments for the PV mma (no smem round trip).
// Keys in 16 chunks of 64; K hi/lo bf16 (stride-12 words), V transposed hi/lo
// bf16 (stride-36 words). Split-bf16 (3 terms) on both mma pairs.
// Softmax via ex2 with log2e folded into Q; l in fp32 via shfl reduction.
// ============================================================================
#define CK 64            // keys per chunk
#define NCHUNK (NKEYS / CK)
#define KSTRIDE 12       // words per K row (8 used + 4 pad)
#define VSTRIDE 72       // halfwords per Vt row (64 used + 8 pad)

__global__ __launch_bounds__(256, 2) void attn_kernel(
    const float* __restrict__ Qh, const float* __restrict__ Kh,
    const float* __restrict__ Vh, float* __restrict__ Oc)
{
    __shared__ uint32_t Khi[CK * KSTRIDE], Klo[CK * KSTRIDE];
    __shared__ unsigned short VtHi[16 * VSTRIDE], VtLo[16 * VSTRIDE];

    const int tid  = threadIdx.x;
    const int wid  = tid >> 5;
    const int lane = tid & 31;
    const int g    = lane >> 2;
    const int t    = lane & 3;

    const int qt  = blockIdx.x;
    const int bth = blockIdx.y;
    const int bt  = bth >> 3, h = bth & 7;

    const float* Qg = Qh + (size_t)bth * 16384;
    const float* Kg = Kh + (size_t)bth * 16384;
    const float* Vg = Vh + (size_t)bth * 16384;

    // ---- load Q fragment (16 rows/warp), prescale by 0.25*log2(e), split ----
    const float sc = 0.25f * 1.4426950408889634f;
    const int rA = qt * 128 + wid * 16 + g;    // query rows of this thread
    const int rB = rA + 8;
    uint32_t aq_hi[4], aq_lo[4];
    {
        float2 xA0 = *(const float2*)(Qg + rA * 16 + 2 * t);
        float2 xB0 = *(const float2*)(Qg + rB * 16 + 2 * t);
        float2 xA1 = *(const float2*)(Qg + rA * 16 + 2 * t + 8);
        float2 xB1 = *(const float2*)(Qg + rB * 16 + 2 * t + 8);
        psplit(xA0.x * sc, xA0.y * sc, aq_hi[0], aq_lo[0]);
        psplit(xB0.x * sc, xB0.y * sc, aq_hi[1], aq_lo[1]);
        psplit(xA1.x * sc, xA1.y * sc, aq_hi[2], aq_lo[2]);
        psplit(xB1.x * sc, xB1.y * sc, aq_hi[3], aq_lo[3]);
    }

    // ---- output accumulators + softmax denominators ----
    float o[2][4];
    #pragma unroll
    for (int j = 0; j < 2; ++j)
        #pragma unroll
        for (int e = 0; e < 4; ++e) o[j][e] = 0.0f;
    float rsA = 0.0f, rsB = 0.0f;

    // staging addresses for this thread: one float4 of K and of V per chunk
    const int srow = tid >> 2;          // 0..63 (key within chunk)
    const int sc4  = tid & 3;           // float4 slot (hd cols 4*sc4..+3)

    // preload chunk 0
    float4 kreg = *(const float4*)(Kg + tid * 4);
    float4 vreg = *(const float4*)(Vg + tid * 4);

    #pragma unroll 1
    for (int cix = 0; cix < NCHUNK; ++cix) {
        if (cix) __syncthreads();        // previous chunk's compute done

        // ---- stage K (hi/lo, row-major) ----
        {
            unsigned short h0, l0, h1, l1, h2, l2, h3, l3;
            bsplit(kreg.x, h0, l0); bsplit(kreg.y, h1, l1);
            bsplit(kreg.z, h2, l2); bsplit(kreg.w, h3, l3);
            int wi = srow * KSTRIDE + sc4 * 2;
            Khi[wi]     = (uint32_t)h0 | ((uint32_t)h1 << 16);
            Khi[wi + 1] = (uint32_t)h2 | ((uint32_t)h3 << 16);
            Klo[wi]     = (uint32_t)l0 | ((uint32_t)l1 << 16);
            Klo[wi + 1] = (uint32_t)l2 | ((uint32_t)l3 << 16);
        }
        // ---- stage V transposed (hi/lo, u16 scatter) ----
        {
            float vs[4] = { vreg.x, vreg.y, vreg.z, vreg.w };
            #pragma unroll
            for (int e = 0; e < 4; ++e) {
                unsigned short hb, lb;
                bsplit(vs[e], hb, lb);
                int col = sc4 * 4 + e;          // hd index
                VtHi[col * VSTRIDE + srow] = hb;
                VtLo[col * VSTRIDE + srow] = lb;
            }
        }
        __syncthreads();

        // prefetch next chunk while computing this one
        if (cix + 1 < NCHUNK) {
            const float* kp = Kg + (cix + 1) * CK * 16 + tid * 4;
            const float* vp = Vg + (cix + 1) * CK * 16 + tid * 4;
            kreg = *(const float4*)kp;
            vreg = *(const float4*)vp;
        }

        // ---- S = Q·K^T for 8 n8-tiles (keys 8i..8i+7), K=16 in one step ----
        float s[8][4];
        #pragma unroll
        for (int i = 0; i < 8; ++i) {
            s[i][0] = 0.0f; s[i][1] = 0.0f; s[i][2] = 0.0f; s[i][3] = 0.0f;
            int b = (8 * i + g) * KSTRIDE + t;
            uint32_t bh0 = Khi[b], bh1 = Khi[b + 4];
            uint32_t bl0 = Klo[b], bl1 = Klo[b + 4];
            mma_bf16(s[i], aq_hi, bh0, bh1);
            mma_bf16(s[i], aq_hi, bl0, bl1);
            mma_bf16(s[i], aq_lo, bh0, bh1);
        }

        // ---- softmax (log2 domain) + PV, interleaved per k16-step ----
        const uint32_t* VtHiW = (const uint32_t*)VtHi;
        const uint32_t* VtLoW = (const uint32_t*)VtLo;
        #pragma unroll
        for (int ks = 0; ks < 4; ++ks) {
            uint32_t ap_hi[4], ap_lo[4];
            #pragma unroll
            for (int half = 0; half < 2; ++half) {
                float* cc = s[2 * ks + half];
                float p0 = ex2(cc[0]), p1 = ex2(cc[1]);
                float p2 = ex2(cc[2]), p3 = ex2(cc[3]);
                rsA += p0 + p1;
                rsB += p2 + p3;
                psplit(p0, p1, ap_hi[2 * half],     ap_lo[2 * half]);
                psplit(p2, p3, ap_hi[2 * half + 1], ap_lo[2 * half + 1]);
            }
            #pragma unroll
            for (int j = 0; j < 2; ++j) {
                int b = (8 * j + g) * (VSTRIDE / 2) + 8 * ks + t;
                uint32_t bh0 = VtHiW[b], bh1 = VtHiW[b + 4];
                uint32_t bl0 = VtLoW[b], bl1 = VtLoW[b + 4];
                mma_bf16(o[j], ap_hi, bh0, bh1);
                mma_bf16(o[j], ap_lo, bh0, bh1);
                mma_bf16(o[j], ap_hi, bl0, bl1);
            }
        }
    }

    // ---- reduce denominators across the 4 threads of each row group ----
    rsA += __shfl_xor_sync(0xffffffffu, rsA, 1);
    rsA += __shfl_xor_sync(0xffffffffu, rsA, 2);
    rsB += __shfl_xor_sync(0xffffffffu, rsB, 1);
    rsB += __shfl_xor_sync(0xffffffffu, rsB, 2);
    const float invA = 1.0f / rsA;
    const float invB = 1.0f / rsB;

    // ---- write O (row-major (r,128) for gemm_o) ----
    #pragma unroll
    for (int j = 0; j < 2; ++j) {
        int col = h * 16 + 8 * j + 2 * t;
        float2 oA = { o[j][0] * invA, o[j][1] * invA };
        float2 oB = { o[j][2] * invB, o[j][3] * invB };
        *(float2*)(Oc + ((size_t)((bt << 10) | rA)) * 128 + col) = oA;
        *(float2*)(Oc + ((size_t)((bt << 10) | rB)) * 128 + col) = oB;
    }
}

// ============================================================================
extern "C" void kernel_launch(void* const* d_in, const int* in_sizes, int n_in,
                              void* d_out, int out_size) {
    const float* query = (const float*)d_in[0];
    const float* key   = (const float*)d_in[1];
    const float* value = (const float*)d_in[2];
    const float* Wq    = (const float*)d_in[3];
    const float* bq    = (const float*)d_in[4];
    const float* Wk    = (const float*)d_in[5];
    const float* bk    = (const float*)d_in[6];
    const float* Wv    = (const float*)d_in[7];
    const float* bv    = (const float*)d_in[8];
    const float* Wo    = (const float*)d_in[9];
    const float* bo    = (const float*)d_in[10];
    float* out = (float*)d_out;

    float *qh, *kh, *vh, *ao;
    cudaGetSymbolAddress((void**)&qh, g_qh);
    cudaGetSymbolAddress((void**)&kh, g_kh);
    cudaGetSymbolAddress((void**)&vh, g_vh);
    cudaGetSymbolAddress((void**)&ao, g_ao);

    gemm_qkv<<<dim3(192, 3), 256>>>(query, key, value,
                                    Wq, Wk, Wv, bq, bk, bv,
                                    qh, kh, vh);
    attn_kernel<<<dim3(8, 192), 256>>>(qh, kh, vh, ao);
    gemm_o<<<192, 256>>>(ao, Wo, bo, out);
}